// round 5
// baseline (speedup 1.0000x reference)
#include <cuda_runtime.h>

#define N_NODES 50000
#define N_EDGES 800000
#define C 128
#define EDGE_DIM 8
#define N_LAYERS 3

// Scratch (device globals; zero-initialized at module load).
// Invariant: g_agg and g_sumw are ZERO at entry to each scatter pass —
// the GEMM kernel re-zeroes them after consuming, so the invariant holds
// across graph replays.
__device__ __align__(16) float g_w[N_LAYERS * N_EDGES];
__device__ __align__(16) float g_agg[N_NODES * C];
__device__ __align__(16) float g_sumw[N_NODES];
__device__ __align__(16) float g_xbuf0[N_NODES * C];
__device__ __align__(16) float g_xbuf1[N_NODES * C];

// ---------------------------------------------------------------------------
// Kernel 1: per-edge softplus weights for all 3 layers in one pass.
// ---------------------------------------------------------------------------
__global__ void edge_weight_kernel(const float* __restrict__ ea,
                                   const float* __restrict__ ew,
                                   const float* __restrict__ eb) {
    int e = blockIdx.x * blockDim.x + threadIdx.x;
    if (e >= N_EDGES) return;
    const float4* ap = (const float4*)(ea + (size_t)e * EDGE_DIM);
    float4 a0 = ap[0];
    float4 a1 = ap[1];
#pragma unroll
    for (int l = 0; l < N_LAYERS; l++) {
        const float* w = ew + l * EDGE_DIM;
        float z = a0.x * w[0] + a0.y * w[1] + a0.z * w[2] + a0.w * w[3] +
                  a1.x * w[4] + a1.y * w[5] + a1.z * w[6] + a1.w * w[7] + eb[l];
        // softplus = log1p(exp(z)), stable for large z
        float sp = (z > 20.0f) ? z : log1pf(__expf(z));
        g_w[l * N_EDGES + e] = sp;
    }
}

// ---------------------------------------------------------------------------
// Kernel 2: scatter. One warp per edge.
//   g_agg[dst] += w * x[src]   (vector red.global.v4.f32.add)
//   g_sumw[dst] += w           (lane 0 scalar atomic)
// The -sumw*x[dst] correction is applied in the GEMM stage.
// NOTE: edge_index is int32 on device (JAX x64 disabled downcasts int64).
// ---------------------------------------------------------------------------
__global__ void scatter_kernel(const float* __restrict__ xin,
                               const int* __restrict__ ei,
                               int layer) {
    int warp = (int)((blockIdx.x * (unsigned)blockDim.x + threadIdx.x) >> 5);
    int lane = threadIdx.x & 31;
    if (warp >= N_EDGES) return;

    int s = __ldg(ei + warp);             // source node
    int d = __ldg(ei + N_EDGES + warp);   // target node
    float wt = __ldg(g_w + (size_t)layer * N_EDGES + warp);

    if (lane == 0) atomicAdd(g_sumw + d, wt);

    float4 v = __ldg((const float4*)(xin + (size_t)s * C) + lane);
    float mx = wt * v.x, my = wt * v.y, mz = wt * v.z, mw = wt * v.w;
    float* p = g_agg + (size_t)d * C + lane * 4;
    asm volatile("red.global.v4.f32.add [%0], {%1,%2,%3,%4};"
                 :: "l"(p), "f"(mx), "f"(my), "f"(mz), "f"(mw)
                 : "memory");
}

// ---------------------------------------------------------------------------
// Kernel 3: fused node update.
//   A[m,:] = agg[m,:] - sumw[m]*xin[m,:]
//   out    = A @ W + b          (+ relu + residual xin for layers 0,1)
// Also zeroes g_agg / g_sumw for the next pass.
// 256 threads, BM=128 rows/block, 8x8 register tile per thread.
// ---------------------------------------------------------------------------
#define BM 128
#define BK 32

__global__ void gemm_kernel(const float* __restrict__ xin,
                            const float* __restrict__ W,     // [C][C] k-major
                            const float* __restrict__ bias,  // [C]
                            float* __restrict__ out,
                            int relu_res) {
    __shared__ float As[BK][BM + 4];
    __shared__ float Ws[BK][C + 4];

    int t = threadIdx.x;
    int tx = t & 15, ty = t >> 4;
    int m0 = blockIdx.x * BM;

    float acc[8][8];
#pragma unroll
    for (int i = 0; i < 8; i++)
#pragma unroll
        for (int j = 0; j < 8; j++) acc[i][j] = 0.0f;

    for (int kc = 0; kc < C; kc += BK) {
        // Load + form A chunk (128 x 32), store k-major; zero agg behind us.
#pragma unroll
        for (int i = 0; i < 4; i++) {
            int m = (t >> 3) + 32 * i;
            int k = (t & 7) << 2;
            int gm = m0 + m;
            if (gm < N_NODES) {
                float sw = g_sumw[gm];
                float4 ag = *(const float4*)(g_agg + (size_t)gm * C + kc + k);
                float4 xv = *(const float4*)(xin + (size_t)gm * C + kc + k);
                As[k + 0][m] = ag.x - sw * xv.x;
                As[k + 1][m] = ag.y - sw * xv.y;
                As[k + 2][m] = ag.z - sw * xv.z;
                As[k + 3][m] = ag.w - sw * xv.w;
                *(float4*)(g_agg + (size_t)gm * C + kc + k) =
                    make_float4(0.f, 0.f, 0.f, 0.f);
            } else {
                As[k + 0][m] = 0.f; As[k + 1][m] = 0.f;
                As[k + 2][m] = 0.f; As[k + 3][m] = 0.f;
            }
        }
        // Load W chunk (32 x 128)
#pragma unroll
        for (int i = 0; i < 4; i++) {
            int idx = t + 256 * i;          // float4 index, 1024 total
            int k = idx >> 5;               // 32 float4 per row
            int n = (idx & 31) << 2;
            float4 wv = *(const float4*)(W + (size_t)(kc + k) * C + n);
            Ws[k][n + 0] = wv.x; Ws[k][n + 1] = wv.y;
            Ws[k][n + 2] = wv.z; Ws[k][n + 3] = wv.w;
        }
        __syncthreads();

#pragma unroll
        for (int k = 0; k < BK; k++) {
            float a[8], b[8];
#pragma unroll
            for (int i = 0; i < 8; i++) a[i] = As[k][ty + 16 * i];
#pragma unroll
            for (int j = 0; j < 8; j++) b[j] = Ws[k][tx + 16 * j];
#pragma unroll
            for (int i = 0; i < 8; i++)
#pragma unroll
                for (int j = 0; j < 8; j++) acc[i][j] += a[i] * b[j];
        }
        __syncthreads();
    }

    // Zero sumw for next layer (all reads of it finished before last sync).
    if (t < BM && m0 + t < N_NODES) g_sumw[m0 + t] = 0.0f;

    // Epilogue: bias, optional relu+residual, store.
#pragma unroll
    for (int i = 0; i < 8; i++) {
        int m = m0 + ty + 16 * i;
        if (m >= N_NODES) continue;
#pragma unroll
        for (int j = 0; j < 8; j++) {
            int n = tx + 16 * j;
            float v = acc[i][j] + bias[n];
            if (relu_res) v = fmaxf(v, 0.0f) + xin[(size_t)m * C + n];
            out[(size_t)m * C + n] = v;
        }
    }
}

// ---------------------------------------------------------------------------
extern "C" void kernel_launch(void* const* d_in, const int* in_sizes, int n_in,
                              void* d_out, int out_size) {
    const float* x = (const float*)d_in[0];
    const int* ei = (const int*)d_in[1];
    const float* ea = (const float*)d_in[2];
    const float* lw = (const float*)d_in[3];
    const float* lb = (const float*)d_in[4];
    const float* ew = (const float*)d_in[5];
    const float* eb = (const float*)d_in[6];
    float* out = (float*)d_out;

    float *xb0, *xb1;
    cudaGetSymbolAddress((void**)&xb0, g_xbuf0);
    cudaGetSymbolAddress((void**)&xb1, g_xbuf1);

    const int EW_BLOCKS = (N_EDGES + 255) / 256;
    const int SC_BLOCKS = (N_EDGES * 32 + 255) / 256;  // warp per edge
    const int GM_BLOCKS = (N_NODES + BM - 1) / BM;

    edge_weight_kernel<<<EW_BLOCKS, 256>>>(ea, ew, eb);

    // layer 0: x -> xb0 (relu + residual)
    scatter_kernel<<<SC_BLOCKS, 256>>>(x, ei, 0);
    gemm_kernel<<<GM_BLOCKS, 256>>>(x, lw, lb, xb0, 1);

    // layer 1: xb0 -> xb1 (relu + residual)
    scatter_kernel<<<SC_BLOCKS, 256>>>(xb0, ei, 1);
    gemm_kernel<<<GM_BLOCKS, 256>>>(xb0, lw + C * C, lb + C, xb1, 1);

    // layer 2: xb1 -> out (plain)
    scatter_kernel<<<SC_BLOCKS, 256>>>(xb1, ei, 2);
    gemm_kernel<<<GM_BLOCKS, 256>>>(xb1, lw + 2 * C * C, lb + 2 * C, out, 0);
}

// round 7
// speedup vs baseline: 2.1185x; 2.1185x over previous
#include <cuda_runtime.h>

#define N_NODES 50000
#define N_EDGES 800000
#define C 128
#define EDGE_DIM 8
#define N_LAYERS 3

#define SCAN_BLK 512
#define SCAN_NB ((N_NODES + SCAN_BLK - 1) / SCAN_BLK)   // 98

// ---------------------------------------------------------------------------
// Scratch (device globals). All fully recomputed every launch.
// ---------------------------------------------------------------------------
__device__ __align__(16) float4 g_sorted[N_EDGES];   // (src, w0, w1, w2), grouped by dst
__device__ int   g_deg[N_NODES];
__device__ int   g_off[N_NODES];
__device__ int   g_cur[N_NODES];
__device__ int   g_bsum[SCAN_NB];
__device__ __align__(16) float g_A[N_NODES * C];     // pre-GEMM operand
__device__ __align__(16) float g_xbuf0[N_NODES * C];
__device__ __align__(16) float g_xbuf1[N_NODES * C];

// ---------------------------------------------------------------------------
// CSR build
// ---------------------------------------------------------------------------
__global__ void zero_deg_kernel() {
    int i = blockIdx.x * blockDim.x + threadIdx.x;
    if (i < N_NODES) g_deg[i] = 0;
}

__global__ void count_kernel(const int* __restrict__ ei) {
    int e = blockIdx.x * blockDim.x + threadIdx.x;
    if (e < N_EDGES) atomicAdd(&g_deg[ei[N_EDGES + e]], 1);
}

// block-local exclusive scan; per-block totals to g_bsum
__global__ void scan_a_kernel() {
    __shared__ int sh[SCAN_BLK];
    int t = threadIdx.x;
    int i = blockIdx.x * SCAN_BLK + t;
    int v = (i < N_NODES) ? g_deg[i] : 0;
    sh[t] = v;
    __syncthreads();
    for (int off = 1; off < SCAN_BLK; off <<= 1) {
        int add = (t >= off) ? sh[t - off] : 0;
        __syncthreads();
        sh[t] += add;
        __syncthreads();
    }
    if (i < N_NODES) g_off[i] = sh[t] - v;           // exclusive within block
    if (t == SCAN_BLK - 1) g_bsum[blockIdx.x] = sh[t];
}

// scan the 98 block sums (single block)
__global__ void scan_b_kernel() {
    __shared__ int sh[128];
    int t = threadIdx.x;
    int v = (t < SCAN_NB) ? g_bsum[t] : 0;
    sh[t] = v;
    __syncthreads();
    for (int off = 1; off < 128; off <<= 1) {
        int add = (t >= off) ? sh[t - off] : 0;
        __syncthreads();
        sh[t] += add;
        __syncthreads();
    }
    if (t < SCAN_NB) g_bsum[t] = sh[t] - v;          // exclusive
}

__global__ void scan_c_kernel() {
    int i = blockIdx.x * blockDim.x + threadIdx.x;
    if (i < N_NODES) {
        int o = g_off[i] + g_bsum[i / SCAN_BLK];
        g_off[i] = o;
        g_cur[i] = o;
    }
}

// Bucket fill: compute all 3 layer softplus weights, pack with src.
__global__ void fill_kernel(const int* __restrict__ ei,
                            const float* __restrict__ ea,
                            const float* __restrict__ ew,
                            const float* __restrict__ eb) {
    int e = blockIdx.x * blockDim.x + threadIdx.x;
    if (e >= N_EDGES) return;
    int s = ei[e];
    int d = ei[N_EDGES + e];
    const float4* ap = (const float4*)(ea + (size_t)e * EDGE_DIM);
    float4 a0 = ap[0];
    float4 a1 = ap[1];
    float w[N_LAYERS];
#pragma unroll
    for (int l = 0; l < N_LAYERS; l++) {
        const float* wl = ew + l * EDGE_DIM;
        float z = a0.x * wl[0] + a0.y * wl[1] + a0.z * wl[2] + a0.w * wl[3] +
                  a1.x * wl[4] + a1.y * wl[5] + a1.z * wl[6] + a1.w * wl[7] + eb[l];
        w[l] = (z > 20.0f) ? z : log1pf(__expf(z));
    }
    int pos = atomicAdd(&g_cur[d], 1);
    g_sorted[pos] = make_float4(__int_as_float(s), w[0], w[1], w[2]);
}

// ---------------------------------------------------------------------------
// Aggregation: warp per node. A[v] = sum_e w_e * x[src_e]  -  (sum_e w_e)*x[v]
// Each lane owns 4 channels; edges broadcast across the warp via shfl.
// ---------------------------------------------------------------------------
__global__ __launch_bounds__(256) void agg_kernel(const float* __restrict__ xin,
                                                  int layer) {
    int warp = (int)((blockIdx.x * (unsigned)blockDim.x + threadIdx.x) >> 5);
    int lane = threadIdx.x & 31;
    if (warp >= N_NODES) return;

    int beg = g_off[warp];
    int end = beg + g_deg[warp];

    float4 acc = make_float4(0.f, 0.f, 0.f, 0.f);
    float swsum = 0.0f;

    for (int j = beg; j < end; j += 32) {
        float4 ed = make_float4(0.f, 0.f, 0.f, 0.f);
        if (j + lane < end) ed = g_sorted[j + lane];
        float wsel = (layer == 0) ? ed.y : ((layer == 1) ? ed.z : ed.w);
        int cnt = min(32, end - j);
        for (int t = 0; t < cnt; t++) {
            int   s  = __shfl_sync(0xffffffffu, __float_as_int(ed.x), t);
            float wt = __shfl_sync(0xffffffffu, wsel, t);
            float4 xv = __ldg((const float4*)(xin + (size_t)s * C) + lane);
            acc.x += wt * xv.x; acc.y += wt * xv.y;
            acc.z += wt * xv.z; acc.w += wt * xv.w;
            swsum += wt;
        }
    }

    float4 xv = __ldg((const float4*)(xin + (size_t)warp * C) + lane);
    acc.x -= swsum * xv.x; acc.y -= swsum * xv.y;
    acc.z -= swsum * xv.z; acc.w -= swsum * xv.w;
    *((float4*)(g_A + (size_t)warp * C) + lane) = acc;
}

// ---------------------------------------------------------------------------
// SGEMM: out[M,C] = A[M,C] @ W[C,C] + b  (+ relu + residual for layers 0,1)
// 128x128 tile, BK=16, 256 threads, 8x8 per thread, vectorized LDS,
// register-prefetch double buffering.
// ---------------------------------------------------------------------------
#define GBM 128
#define GBK 16

__global__ __launch_bounds__(256) void gemm_kernel(const float* __restrict__ xin,
                                                   const float* __restrict__ W,
                                                   const float* __restrict__ bias,
                                                   float* __restrict__ out,
                                                   int relu_res) {
    __shared__ float As[GBK][GBM + 4];
    __shared__ float Ws[GBK][GBM];

    int t = threadIdx.x;
    int tx = t & 15, ty = t >> 4;
    int m0 = blockIdx.x * GBM;

    // load index precompute
    int arow[2], akq[2], wk[2], wn[2];
#pragma unroll
    for (int i = 0; i < 2; i++) {
        int idx = t + 256 * i;
        arow[i] = idx >> 2;            // 0..127
        akq[i]  = idx & 3;             // float4 within 16-k chunk
        wk[i]   = idx >> 5;            // 0..15
        wn[i]   = (idx & 31) << 2;     // 0..124
    }

    float acc[8][8];
#pragma unroll
    for (int i = 0; i < 8; i++)
#pragma unroll
        for (int j = 0; j < 8; j++) acc[i][j] = 0.0f;

    float4 pa[2], pw[2];
#pragma unroll
    for (int i = 0; i < 2; i++) {
        int gm = m0 + arow[i];
        pa[i] = (gm < N_NODES)
                    ? __ldg((const float4*)(g_A + (size_t)gm * C + akq[i] * 4))
                    : make_float4(0.f, 0.f, 0.f, 0.f);
        pw[i] = __ldg((const float4*)(W + (size_t)wk[i] * C + wn[i]));
    }

    for (int kc = 0; kc < C; kc += GBK) {
        // commit prefetched chunk to smem
#pragma unroll
        for (int i = 0; i < 2; i++) {
            int kb = akq[i] * 4;
            As[kb + 0][arow[i]] = pa[i].x;
            As[kb + 1][arow[i]] = pa[i].y;
            As[kb + 2][arow[i]] = pa[i].z;
            As[kb + 3][arow[i]] = pa[i].w;
            *(float4*)&Ws[wk[i]][wn[i]] = pw[i];
        }
        __syncthreads();

        // prefetch next chunk
        if (kc + GBK < C) {
#pragma unroll
            for (int i = 0; i < 2; i++) {
                int gm = m0 + arow[i];
                pa[i] = (gm < N_NODES)
                            ? __ldg((const float4*)(g_A + (size_t)gm * C +
                                                    (kc + GBK) + akq[i] * 4))
                            : make_float4(0.f, 0.f, 0.f, 0.f);
                pw[i] = __ldg((const float4*)(W + (size_t)(kc + GBK + wk[i]) * C +
                                              wn[i]));
            }
        }

#pragma unroll
        for (int k = 0; k < GBK; k++) {
            float4 a0 = *(const float4*)&As[k][ty * 4];
            float4 a1 = *(const float4*)&As[k][ty * 4 + 64];
            float4 b0 = *(const float4*)&Ws[k][tx * 4];
            float4 b1 = *(const float4*)&Ws[k][tx * 4 + 64];
            float av[8] = {a0.x, a0.y, a0.z, a0.w, a1.x, a1.y, a1.z, a1.w};
            float bv[8] = {b0.x, b0.y, b0.z, b0.w, b1.x, b1.y, b1.z, b1.w};
#pragma unroll
            for (int i = 0; i < 8; i++)
#pragma unroll
                for (int j = 0; j < 8; j++) acc[i][j] += av[i] * bv[j];
        }
        __syncthreads();
    }

    // epilogue
    float4 bb[2];
    bb[0] = __ldg((const float4*)(bias + tx * 4));
    bb[1] = __ldg((const float4*)(bias + tx * 4 + 64));

#pragma unroll
    for (int hi = 0; hi < 2; hi++) {
#pragma unroll
        for (int ii = 0; ii < 4; ii++) {
            int m = m0 + ty * 4 + ii + hi * 64;
            if (m >= N_NODES) continue;
            int ai = hi * 4 + ii;
#pragma unroll
            for (int hj = 0; hj < 2; hj++) {
                int n = tx * 4 + hj * 64;
                float4 v;
                v.x = acc[ai][hj * 4 + 0] + ((const float*)&bb[hj])[0];
                v.y = acc[ai][hj * 4 + 1] + ((const float*)&bb[hj])[1];
                v.z = acc[ai][hj * 4 + 2] + ((const float*)&bb[hj])[2];
                v.w = acc[ai][hj * 4 + 3] + ((const float*)&bb[hj])[3];
                if (relu_res) {
                    float4 r = __ldg((const float4*)(xin + (size_t)m * C + n));
                    v.x = fmaxf(v.x, 0.f) + r.x;
                    v.y = fmaxf(v.y, 0.f) + r.y;
                    v.z = fmaxf(v.z, 0.f) + r.z;
                    v.w = fmaxf(v.w, 0.f) + r.w;
                }
                *(float4*)(out + (size_t)m * C + n) = v;
            }
        }
    }
}

// ---------------------------------------------------------------------------
extern "C" void kernel_launch(void* const* d_in, const int* in_sizes, int n_in,
                              void* d_out, int out_size) {
    const float* x  = (const float*)d_in[0];
    const int*   ei = (const int*)d_in[1];
    const float* ea = (const float*)d_in[2];
    const float* lw = (const float*)d_in[3];
    const float* lb = (const float*)d_in[4];
    const float* ew = (const float*)d_in[5];
    const float* eb = (const float*)d_in[6];
    float* out = (float*)d_out;

    float *xb0, *xb1;
    cudaGetSymbolAddress((void**)&xb0, g_xbuf0);
    cudaGetSymbolAddress((void**)&xb1, g_xbuf1);

    const int NODE_BLOCKS = (N_NODES + 255) / 256;
    const int EDGE_BLOCKS = (N_EDGES + 255) / 256;
    const int AGG_BLOCKS  = (N_NODES + 7) / 8;        // warp per node, 8 warps/blk
    const int GM_BLOCKS   = (N_NODES + GBM - 1) / GBM;

    // CSR build (by dst) + edge weights
    zero_deg_kernel<<<NODE_BLOCKS, 256>>>();
    count_kernel<<<EDGE_BLOCKS, 256>>>(ei);
    scan_a_kernel<<<SCAN_NB, SCAN_BLK>>>();
    scan_b_kernel<<<1, 128>>>();
    scan_c_kernel<<<NODE_BLOCKS, 256>>>();
    fill_kernel<<<EDGE_BLOCKS, 256>>>(ei, ea, ew, eb);

    // layer 0: x -> xb0 (relu + residual)
    agg_kernel<<<AGG_BLOCKS, 256>>>(x, 0);
    gemm_kernel<<<GM_BLOCKS, 256>>>(x, lw, lb, xb0, 1);

    // layer 1: xb0 -> xb1 (relu + residual)
    agg_kernel<<<AGG_BLOCKS, 256>>>(xb0, 1);
    gemm_kernel<<<GM_BLOCKS, 256>>>(xb0, lw + C * C, lb + C, xb1, 1);

    // layer 2: xb1 -> out (plain)
    agg_kernel<<<AGG_BLOCKS, 256>>>(xb1, 2);
    gemm_kernel<<<GM_BLOCKS, 256>>>(xb1, lw + 2 * C * C, lb + 2 * C, out, 0);
}

// round 10
// speedup vs baseline: 2.2596x; 1.0666x over previous
#include <cuda_runtime.h>

#define N_NODES 50000
#define N_EDGES 800000
#define C 128
#define EDGE_DIM 8
#define N_LAYERS 3

#define SCAN_BLK 512
#define SCAN_NB ((N_NODES + SCAN_BLK - 1) / SCAN_BLK)   // 98

// ---------------------------------------------------------------------------
// Scratch (device globals). All fully recomputed every launch.
// ---------------------------------------------------------------------------
__device__ __align__(16) float4 g_sorted[N_EDGES];   // (src, w0, w1, w2) grouped by dst
__device__ int   g_deg[N_NODES];
__device__ int   g_off[N_NODES];
__device__ int   g_cur[N_NODES];
__device__ int   g_bsum[SCAN_NB];
__device__ __align__(16) float g_y[N_NODES * C];     // y = x @ W (pre-agg operand)
__device__ __align__(16) float g_xbuf0[N_NODES * C];
__device__ __align__(16) float g_xbuf1[N_NODES * C];

// ---------------------------------------------------------------------------
// CSR build
// ---------------------------------------------------------------------------
__global__ void zero_deg_kernel() {
    int i = blockIdx.x * blockDim.x + threadIdx.x;
    if (i < N_NODES) g_deg[i] = 0;
}

__global__ void count_kernel(const int* __restrict__ ei) {
    int q = blockIdx.x * blockDim.x + threadIdx.x;      // int4 index
    if (q * 4 >= N_EDGES) return;
    int4 d4 = __ldg((const int4*)(ei + N_EDGES) + q);
    atomicAdd(&g_deg[d4.x], 1);
    atomicAdd(&g_deg[d4.y], 1);
    atomicAdd(&g_deg[d4.z], 1);
    atomicAdd(&g_deg[d4.w], 1);
}

__global__ void scan_a_kernel() {
    __shared__ int sh[SCAN_BLK];
    int t = threadIdx.x;
    int i = blockIdx.x * SCAN_BLK + t;
    int v = (i < N_NODES) ? g_deg[i] : 0;
    sh[t] = v;
    __syncthreads();
    for (int off = 1; off < SCAN_BLK; off <<= 1) {
        int add = (t >= off) ? sh[t - off] : 0;
        __syncthreads();
        sh[t] += add;
        __syncthreads();
    }
    if (i < N_NODES) g_off[i] = sh[t] - v;
    if (t == SCAN_BLK - 1) g_bsum[blockIdx.x] = sh[t];
}

__global__ void scan_b_kernel() {
    __shared__ int sh[128];
    int t = threadIdx.x;
    int v = (t < SCAN_NB) ? g_bsum[t] : 0;
    sh[t] = v;
    __syncthreads();
    for (int off = 1; off < 128; off <<= 1) {
        int add = (t >= off) ? sh[t - off] : 0;
        __syncthreads();
        sh[t] += add;
        __syncthreads();
    }
    if (t < SCAN_NB) g_bsum[t] = sh[t] - v;
}

__global__ void scan_c_kernel() {
    int i = blockIdx.x * blockDim.x + threadIdx.x;
    if (i < N_NODES) {
        int o = g_off[i] + g_bsum[i / SCAN_BLK];
        g_off[i] = o;
        g_cur[i] = o;
    }
}

__global__ void fill_kernel(const int* __restrict__ ei,
                            const float* __restrict__ ea,
                            const float* __restrict__ ew,
                            const float* __restrict__ eb) {
    int e = blockIdx.x * blockDim.x + threadIdx.x;
    if (e >= N_EDGES) return;
    int s = __ldg(ei + e);
    int d = __ldg(ei + N_EDGES + e);
    const float4* ap = (const float4*)(ea + (size_t)e * EDGE_DIM);
    float4 a0 = ap[0];
    float4 a1 = ap[1];
    float w[N_LAYERS];
#pragma unroll
    for (int l = 0; l < N_LAYERS; l++) {
        const float* wl = ew + l * EDGE_DIM;
        float z = a0.x * wl[0] + a0.y * wl[1] + a0.z * wl[2] + a0.w * wl[3] +
                  a1.x * wl[4] + a1.y * wl[5] + a1.z * wl[6] + a1.w * wl[7] + eb[l];
        w[l] = (z > 20.0f) ? z : log1pf(__expf(z));
    }
    int pos = atomicAdd(&g_cur[d], 1);
    g_sorted[pos] = make_float4(__int_as_float(s), w[0], w[1], w[2]);
}

// ---------------------------------------------------------------------------
// Aggregation over y = x@W, with fused epilogue. Warp per node.
//   out[v] = f( sum_e w_e*y[src_e] - (sum_e w_e)*y[v] + b )
//   f = relu(.)+xres[v]   (layers 0,1)   or identity (layer 2)
// ---------------------------------------------------------------------------
__global__ __launch_bounds__(256) void agg_kernel(const float* __restrict__ y,
                                                  const float* __restrict__ xres,
                                                  const float* __restrict__ bias,
                                                  float* __restrict__ out,
                                                  int layer, int relu_res) {
    int node = (int)((blockIdx.x * (unsigned)blockDim.x + threadIdx.x) >> 5);
    int lane = threadIdx.x & 31;
    if (node >= N_NODES) return;

    int beg = g_off[node];
    int end = beg + g_deg[node];

    float4 acc = make_float4(0.f, 0.f, 0.f, 0.f);
    float swsum = 0.0f;

    for (int j = beg; j < end; j += 32) {
        float4 ed = make_float4(0.f, 0.f, 0.f, 0.f);
        if (j + lane < end) ed = g_sorted[j + lane];
        float wsel = (layer == 0) ? ed.y : ((layer == 1) ? ed.z : ed.w);
        int cnt = min(32, end - j);
        int t = 0;
        // unroll by 4: 4 independent gathers in flight per lane
        for (; t + 4 <= cnt; t += 4) {
            int   s0 = __shfl_sync(0xffffffffu, __float_as_int(ed.x), t + 0);
            int   s1 = __shfl_sync(0xffffffffu, __float_as_int(ed.x), t + 1);
            int   s2 = __shfl_sync(0xffffffffu, __float_as_int(ed.x), t + 2);
            int   s3 = __shfl_sync(0xffffffffu, __float_as_int(ed.x), t + 3);
            float w0 = __shfl_sync(0xffffffffu, wsel, t + 0);
            float w1 = __shfl_sync(0xffffffffu, wsel, t + 1);
            float w2 = __shfl_sync(0xffffffffu, wsel, t + 2);
            float w3 = __shfl_sync(0xffffffffu, wsel, t + 3);
            float4 v0 = __ldg((const float4*)(y + (size_t)s0 * C) + lane);
            float4 v1 = __ldg((const float4*)(y + (size_t)s1 * C) + lane);
            float4 v2 = __ldg((const float4*)(y + (size_t)s2 * C) + lane);
            float4 v3 = __ldg((const float4*)(y + (size_t)s3 * C) + lane);
            acc.x += w0 * v0.x; acc.y += w0 * v0.y; acc.z += w0 * v0.z; acc.w += w0 * v0.w;
            acc.x += w1 * v1.x; acc.y += w1 * v1.y; acc.z += w1 * v1.z; acc.w += w1 * v1.w;
            acc.x += w2 * v2.x; acc.y += w2 * v2.y; acc.z += w2 * v2.z; acc.w += w2 * v2.w;
            acc.x += w3 * v3.x; acc.y += w3 * v3.y; acc.z += w3 * v3.z; acc.w += w3 * v3.w;
            swsum += w0 + w1 + w2 + w3;
        }
        for (; t < cnt; t++) {
            int   s  = __shfl_sync(0xffffffffu, __float_as_int(ed.x), t);
            float wt = __shfl_sync(0xffffffffu, wsel, t);
            float4 xv = __ldg((const float4*)(y + (size_t)s * C) + lane);
            acc.x += wt * xv.x; acc.y += wt * xv.y;
            acc.z += wt * xv.z; acc.w += wt * xv.w;
            swsum += wt;
        }
    }

    float4 yv = __ldg((const float4*)(y + (size_t)node * C) + lane);
    float4 bb = __ldg((const float4*)(bias) + lane);
    float4 v;
    v.x = acc.x - swsum * yv.x + bb.x;
    v.y = acc.y - swsum * yv.y + bb.y;
    v.z = acc.z - swsum * yv.z + bb.z;
    v.w = acc.w - swsum * yv.w + bb.w;
    if (relu_res) {
        float4 r = __ldg((const float4*)(xres + (size_t)node * C) + lane);
        v.x = fmaxf(v.x, 0.f) + r.x;
        v.y = fmaxf(v.y, 0.f) + r.y;
        v.z = fmaxf(v.z, 0.f) + r.z;
        v.w = fmaxf(v.w, 0.f) + r.w;
    }
    *((float4*)(out + (size_t)node * C) + lane) = v;
}

// ---------------------------------------------------------------------------
// SGEMM: y[M,C] = X[M,C] @ W[C,C]   (no epilogue — fused into agg)
// 128x128 tile, BK=16, 256 threads, 8x8/thread, register double buffering.
// ---------------------------------------------------------------------------
#define GBM 128
#define GBK 16

__global__ __launch_bounds__(256) void gemm_kernel(const float* __restrict__ X,
                                                   const float* __restrict__ W,
                                                   float* __restrict__ Y) {
    __shared__ float As[GBK][GBM + 4];
    __shared__ float Ws[GBK][GBM];

    int t = threadIdx.x;
    int tx = t & 15, ty = t >> 4;
    int m0 = blockIdx.x * GBM;

    int arow[2], akq[2], wk[2], wn[2];
#pragma unroll
    for (int i = 0; i < 2; i++) {
        int idx = t + 256 * i;
        arow[i] = idx >> 2;
        akq[i]  = idx & 3;
        wk[i]   = idx >> 5;
        wn[i]   = (idx & 31) << 2;
    }

    float acc[8][8];
#pragma unroll
    for (int i = 0; i < 8; i++)
#pragma unroll
        for (int j = 0; j < 8; j++) acc[i][j] = 0.0f;

    float4 pa[2], pw[2];
#pragma unroll
    for (int i = 0; i < 2; i++) {
        int gm = m0 + arow[i];
        pa[i] = (gm < N_NODES)
                    ? __ldg((const float4*)(X + (size_t)gm * C + akq[i] * 4))
                    : make_float4(0.f, 0.f, 0.f, 0.f);
        pw[i] = __ldg((const float4*)(W + (size_t)wk[i] * C + wn[i]));
    }

    for (int kc = 0; kc < C; kc += GBK) {
#pragma unroll
        for (int i = 0; i < 2; i++) {
            int kb = akq[i] * 4;
            As[kb + 0][arow[i]] = pa[i].x;
            As[kb + 1][arow[i]] = pa[i].y;
            As[kb + 2][arow[i]] = pa[i].z;
            As[kb + 3][arow[i]] = pa[i].w;
            *(float4*)&Ws[wk[i]][wn[i]] = pw[i];
        }
        __syncthreads();

        if (kc + GBK < C) {
#pragma unroll
            for (int i = 0; i < 2; i++) {
                int gm = m0 + arow[i];
                pa[i] = (gm < N_NODES)
                            ? __ldg((const float4*)(X + (size_t)gm * C +
                                                    (kc + GBK) + akq[i] * 4))
                            : make_float4(0.f, 0.f, 0.f, 0.f);
                pw[i] = __ldg((const float4*)(W + (size_t)(kc + GBK + wk[i]) * C +
                                              wn[i]));
            }
        }

#pragma unroll
        for (int k = 0; k < GBK; k++) {
            float4 a0 = *(const float4*)&As[k][ty * 4];
            float4 a1 = *(const float4*)&As[k][ty * 4 + 64];
            float4 b0 = *(const float4*)&Ws[k][tx * 4];
            float4 b1 = *(const float4*)&Ws[k][tx * 4 + 64];
            float av[8] = {a0.x, a0.y, a0.z, a0.w, a1.x, a1.y, a1.z, a1.w};
            float bv[8] = {b0.x, b0.y, b0.z, b0.w, b1.x, b1.y, b1.z, b1.w};
#pragma unroll
            for (int i = 0; i < 8; i++)
#pragma unroll
                for (int j = 0; j < 8; j++) acc[i][j] += av[i] * bv[j];
        }
        __syncthreads();
    }

#pragma unroll
    for (int hi = 0; hi < 2; hi++) {
#pragma unroll
        for (int ii = 0; ii < 4; ii++) {
            int m = m0 + ty * 4 + ii + hi * 64;
            if (m >= N_NODES) continue;
            int ai = hi * 4 + ii;
#pragma unroll
            for (int hj = 0; hj < 2; hj++) {
                int n = tx * 4 + hj * 64;
                float4 v = make_float4(acc[ai][hj * 4 + 0], acc[ai][hj * 4 + 1],
                                       acc[ai][hj * 4 + 2], acc[ai][hj * 4 + 3]);
                *(float4*)(Y + (size_t)m * C + n) = v;
            }
        }
    }
}

// ---------------------------------------------------------------------------
extern "C" void kernel_launch(void* const* d_in, const int* in_sizes, int n_in,
                              void* d_out, int out_size) {
    const float* x  = (const float*)d_in[0];
    const int*   ei = (const int*)d_in[1];
    const float* ea = (const float*)d_in[2];
    const float* lw = (const float*)d_in[3];
    const float* lb = (const float*)d_in[4];
    const float* ew = (const float*)d_in[5];
    const float* eb = (const float*)d_in[6];
    float* out = (float*)d_out;

    float *yA, *xb0, *xb1;
    cudaGetSymbolAddress((void**)&yA, g_y);
    cudaGetSymbolAddress((void**)&xb0, g_xbuf0);
    cudaGetSymbolAddress((void**)&xb1, g_xbuf1);

    const int NODE_BLOCKS = (N_NODES + 255) / 256;
    const int EDGE_BLOCKS = (N_EDGES + 255) / 256;
    const int CNT_BLOCKS  = (N_EDGES / 4 + 255) / 256;
    const int AGG_BLOCKS  = (N_NODES + 7) / 8;        // warp/node, 8 warps/blk
    const int GM_BLOCKS   = (N_NODES + GBM - 1) / GBM;

    // One-time lazy creation of the side stream + fork/join events.
    // (Created outside any capture on the first (correctness) call; reused
    //  verbatim on the capture call so no resources are created mid-capture.)
    struct Res {
        cudaStream_t s2;
        cudaEvent_t evFork, evJoin;
        Res() {
            cudaStreamCreateWithFlags(&s2, cudaStreamNonBlocking);
            cudaEventCreateWithFlags(&evFork, cudaEventDisableTiming);
            cudaEventCreateWithFlags(&evJoin, cudaEventDisableTiming);
        }
    };
    static Res r;

    // Fork: gemm0 (y0 = x@W0) runs concurrently with the CSR build.
    cudaEventRecord(r.evFork, 0);
    cudaStreamWaitEvent(r.s2, r.evFork, 0);
    gemm_kernel<<<GM_BLOCKS, 256, 0, r.s2>>>(x, lw, yA);
    cudaEventRecord(r.evJoin, r.s2);

    // CSR build (by dst) + per-edge softplus weights, on the capture stream.
    zero_deg_kernel<<<NODE_BLOCKS, 256>>>();
    count_kernel<<<CNT_BLOCKS, 256>>>(ei);
    scan_a_kernel<<<SCAN_NB, SCAN_BLK>>>();
    scan_b_kernel<<<1, 128>>>();
    scan_c_kernel<<<NODE_BLOCKS, 256>>>();
    fill_kernel<<<EDGE_BLOCKS, 256>>>(ei, ea, ew, eb);

    cudaStreamWaitEvent(0, r.evJoin, 0);

    // layer 0: agg over y0, relu+residual(x) -> xb0
    agg_kernel<<<AGG_BLOCKS, 256>>>(yA, x, lb, xb0, 0, 1);

    // layer 1
    gemm_kernel<<<GM_BLOCKS, 256>>>(xb0, lw + C * C, yA);
    agg_kernel<<<AGG_BLOCKS, 256>>>(yA, xb0, lb + C, xb1, 1, 1);

    // layer 2 (no relu/residual)
    gemm_kernel<<<GM_BLOCKS, 256>>>(xb1, lw + 2 * C * C, yA);
    agg_kernel<<<AGG_BLOCKS, 256>>>(yA, xb1, lb + 2 * C, out, 2, 0);
}

// round 11
// speedup vs baseline: 2.6943x; 1.1924x over previous
#include <cuda_runtime.h>
#include <cuda_fp16.h>

#define N_NODES 50000
#define N_EDGES 800000
#define C 128
#define EDGE_DIM 8
#define N_LAYERS 3

#define SCAN_BLK 512
#define SCAN_NB ((N_NODES + SCAN_BLK - 1) / SCAN_BLK)   // 98

// ---------------------------------------------------------------------------
// Scratch (device globals). All fully recomputed every launch.
// ---------------------------------------------------------------------------
__device__ __align__(16) float4 g_sorted[N_EDGES];   // (src, w0, w1, w2) grouped by dst
__device__ int   g_deg[N_NODES];
__device__ int   g_off[N_NODES];
__device__ int   g_cur[N_NODES];
__device__ int   g_bsum[SCAN_NB];
__device__ __align__(16) __half g_y[N_NODES * C];    // y = x @ W, fp16 staged
__device__ __align__(16) float g_xbuf0[N_NODES * C];
__device__ __align__(16) float g_xbuf1[N_NODES * C];

// ---------------------------------------------------------------------------
// CSR build
// ---------------------------------------------------------------------------
__global__ void zero_deg_kernel() {
    int i = blockIdx.x * blockDim.x + threadIdx.x;
    if (i < N_NODES) g_deg[i] = 0;
}

__global__ void count_kernel(const int* __restrict__ ei) {
    int q = blockIdx.x * blockDim.x + threadIdx.x;      // int4 index
    if (q * 4 >= N_EDGES) return;
    int4 d4 = __ldg((const int4*)(ei + N_EDGES) + q);
    atomicAdd(&g_deg[d4.x], 1);
    atomicAdd(&g_deg[d4.y], 1);
    atomicAdd(&g_deg[d4.z], 1);
    atomicAdd(&g_deg[d4.w], 1);
}

__global__ void scan_a_kernel() {
    __shared__ int sh[SCAN_BLK];
    int t = threadIdx.x;
    int i = blockIdx.x * SCAN_BLK + t;
    int v = (i < N_NODES) ? g_deg[i] : 0;
    sh[t] = v;
    __syncthreads();
    for (int off = 1; off < SCAN_BLK; off <<= 1) {
        int add = (t >= off) ? sh[t - off] : 0;
        __syncthreads();
        sh[t] += add;
        __syncthreads();
    }
    if (i < N_NODES) g_off[i] = sh[t] - v;
    if (t == SCAN_BLK - 1) g_bsum[blockIdx.x] = sh[t];
}

__global__ void scan_b_kernel() {
    __shared__ int sh[128];
    int t = threadIdx.x;
    int v = (t < SCAN_NB) ? g_bsum[t] : 0;
    sh[t] = v;
    __syncthreads();
    for (int off = 1; off < 128; off <<= 1) {
        int add = (t >= off) ? sh[t - off] : 0;
        __syncthreads();
        sh[t] += add;
        __syncthreads();
    }
    if (t < SCAN_NB) g_bsum[t] = sh[t] - v;
}

__global__ void scan_c_kernel() {
    int i = blockIdx.x * blockDim.x + threadIdx.x;
    if (i < N_NODES) {
        int o = g_off[i] + g_bsum[i / SCAN_BLK];
        g_off[i] = o;
        g_cur[i] = o;
    }
}

__global__ void fill_kernel(const int* __restrict__ ei,
                            const float* __restrict__ ea,
                            const float* __restrict__ ew,
                            const float* __restrict__ eb) {
    int e = blockIdx.x * blockDim.x + threadIdx.x;
    if (e >= N_EDGES) return;
    int s = __ldg(ei + e);
    int d = __ldg(ei + N_EDGES + e);
    const float4* ap = (const float4*)(ea + (size_t)e * EDGE_DIM);
    float4 a0 = ap[0];
    float4 a1 = ap[1];
    float w[N_LAYERS];
#pragma unroll
    for (int l = 0; l < N_LAYERS; l++) {
        const float* wl = ew + l * EDGE_DIM;
        float z = a0.x * wl[0] + a0.y * wl[1] + a0.z * wl[2] + a0.w * wl[3] +
                  a1.x * wl[4] + a1.y * wl[5] + a1.z * wl[6] + a1.w * wl[7] + eb[l];
        w[l] = (z > 20.0f) ? z : log1pf(__expf(z));
    }
    int pos = atomicAdd(&g_cur[d], 1);
    g_sorted[pos] = make_float4(__int_as_float(s), w[0], w[1], w[2]);
}

// ---------------------------------------------------------------------------
// Aggregation over fp16 y = x@W, fp32 accumulation, fused epilogue.
// Warp per node:
//   out[v] = f( sum_e w_e*y[src_e] - (sum_e w_e)*y[v] + b )
//   f = relu(.)+xres[v]   (layers 0,1)   or identity (layer 2)
// ---------------------------------------------------------------------------
__device__ __forceinline__ void acc_edge(float4& acc, float w, uint2 raw) {
    float2 f0 = __half22float2(*(__half2*)&raw.x);
    float2 f1 = __half22float2(*(__half2*)&raw.y);
    acc.x += w * f0.x; acc.y += w * f0.y;
    acc.z += w * f1.x; acc.w += w * f1.y;
}

template <int LAYER, int RELU_RES>
__global__ __launch_bounds__(256) void agg_kernel(const __half* __restrict__ y,
                                                  const float* __restrict__ xres,
                                                  const float* __restrict__ bias,
                                                  float* __restrict__ out) {
    int node = (int)((blockIdx.x * (unsigned)blockDim.x + threadIdx.x) >> 5);
    int lane = threadIdx.x & 31;
    if (node >= N_NODES) return;

    int beg = g_off[node];
    int end = beg + g_deg[node];

    float4 acc = make_float4(0.f, 0.f, 0.f, 0.f);
    float swsum = 0.0f;

    for (int j = beg; j < end; j += 32) {
        float4 ed = make_float4(0.f, 0.f, 0.f, 0.f);
        if (j + lane < end) ed = g_sorted[j + lane];
        float wsel = (LAYER == 0) ? ed.y : ((LAYER == 1) ? ed.z : ed.w);
        int cnt = min(32, end - j);
        int t = 0;
        for (; t + 4 <= cnt; t += 4) {
            int   s0 = __shfl_sync(0xffffffffu, __float_as_int(ed.x), t + 0);
            int   s1 = __shfl_sync(0xffffffffu, __float_as_int(ed.x), t + 1);
            int   s2 = __shfl_sync(0xffffffffu, __float_as_int(ed.x), t + 2);
            int   s3 = __shfl_sync(0xffffffffu, __float_as_int(ed.x), t + 3);
            float w0 = __shfl_sync(0xffffffffu, wsel, t + 0);
            float w1 = __shfl_sync(0xffffffffu, wsel, t + 1);
            float w2 = __shfl_sync(0xffffffffu, wsel, t + 2);
            float w3 = __shfl_sync(0xffffffffu, wsel, t + 3);
            uint2 r0 = __ldg((const uint2*)(y + (size_t)s0 * C) + lane);
            uint2 r1 = __ldg((const uint2*)(y + (size_t)s1 * C) + lane);
            uint2 r2 = __ldg((const uint2*)(y + (size_t)s2 * C) + lane);
            uint2 r3 = __ldg((const uint2*)(y + (size_t)s3 * C) + lane);
            acc_edge(acc, w0, r0);
            acc_edge(acc, w1, r1);
            acc_edge(acc, w2, r2);
            acc_edge(acc, w3, r3);
            swsum += w0 + w1 + w2 + w3;
        }
        for (; t < cnt; t++) {
            int   s  = __shfl_sync(0xffffffffu, __float_as_int(ed.x), t);
            float wt = __shfl_sync(0xffffffffu, wsel, t);
            uint2 r = __ldg((const uint2*)(y + (size_t)s * C) + lane);
            acc_edge(acc, wt, r);
            swsum += wt;
        }
    }

    uint2 rv = __ldg((const uint2*)(y + (size_t)node * C) + lane);
    float2 yv0 = __half22float2(*(__half2*)&rv.x);
    float2 yv1 = __half22float2(*(__half2*)&rv.y);
    float4 bb = __ldg((const float4*)(bias) + lane);
    float4 v;
    v.x = acc.x - swsum * yv0.x + bb.x;
    v.y = acc.y - swsum * yv0.y + bb.y;
    v.z = acc.z - swsum * yv1.x + bb.z;
    v.w = acc.w - swsum * yv1.y + bb.w;
    if (RELU_RES) {
        float4 r = __ldg((const float4*)(xres + (size_t)node * C) + lane);
        v.x = fmaxf(v.x, 0.f) + r.x;
        v.y = fmaxf(v.y, 0.f) + r.y;
        v.z = fmaxf(v.z, 0.f) + r.z;
        v.w = fmaxf(v.w, 0.f) + r.w;
    }
    *((float4*)(out + (size_t)node * C) + lane) = v;
}

// ---------------------------------------------------------------------------
// SGEMM: y[M,C] = X[M,C] @ W[C,C], fp32 compute, fp16 output.
// 128x128 tile, BK=16, 256 threads, 8x8/thread, register double buffering.
// ---------------------------------------------------------------------------
#define GBM 128
#define GBK 16

__global__ __launch_bounds__(256) void gemm_kernel(const float* __restrict__ X,
                                                   const float* __restrict__ W,
                                                   __half* __restrict__ Y) {
    __shared__ float As[GBK][GBM + 4];
    __shared__ float Ws[GBK][GBM];

    int t = threadIdx.x;
    int tx = t & 15, ty = t >> 4;
    int m0 = blockIdx.x * GBM;

    int arow[2], akq[2], wk[2], wn[2];
#pragma unroll
    for (int i = 0; i < 2; i++) {
        int idx = t + 256 * i;
        arow[i] = idx >> 2;
        akq[i]  = idx & 3;
        wk[i]   = idx >> 5;
        wn[i]   = (idx & 31) << 2;
    }

    float acc[8][8];
#pragma unroll
    for (int i = 0; i < 8; i++)
#pragma unroll
        for (int j = 0; j < 8; j++) acc[i][j] = 0.0f;

    float4 pa[2], pw[2];
#pragma unroll
    for (int i = 0; i < 2; i++) {
        int gm = m0 + arow[i];
        pa[i] = (gm < N_NODES)
                    ? __ldg((const float4*)(X + (size_t)gm * C + akq[i] * 4))
                    : make_float4(0.f, 0.f, 0.f, 0.f);
        pw[i] = __ldg((const float4*)(W + (size_t)wk[i] * C + wn[i]));
    }

    for (int kc = 0; kc < C; kc += GBK) {
#pragma unroll
        for (int i = 0; i < 2; i++) {
            int kb = akq[i] * 4;
            As[kb + 0][arow[i]] = pa[i].x;
            As[kb + 1][arow[i]] = pa[i].y;
            As[kb + 2][arow[i]] = pa[i].z;
            As[kb + 3][arow[i]] = pa[i].w;
            *(float4*)&Ws[wk[i]][wn[i]] = pw[i];
        }
        __syncthreads();

        if (kc + GBK < C) {
#pragma unroll
            for (int i = 0; i < 2; i++) {
                int gm = m0 + arow[i];
                pa[i] = (gm < N_NODES)
                            ? __ldg((const float4*)(X + (size_t)gm * C +
                                                    (kc + GBK) + akq[i] * 4))
                            : make_float4(0.f, 0.f, 0.f, 0.f);
                pw[i] = __ldg((const float4*)(W + (size_t)(kc + GBK + wk[i]) * C +
                                              wn[i]));
            }
        }

#pragma unroll
        for (int k = 0; k < GBK; k++) {
            float4 a0 = *(const float4*)&As[k][ty * 4];
            float4 a1 = *(const float4*)&As[k][ty * 4 + 64];
            float4 b0 = *(const float4*)&Ws[k][tx * 4];
            float4 b1 = *(const float4*)&Ws[k][tx * 4 + 64];
            float av[8] = {a0.x, a0.y, a0.z, a0.w, a1.x, a1.y, a1.z, a1.w};
            float bv[8] = {b0.x, b0.y, b0.z, b0.w, b1.x, b1.y, b1.z, b1.w};
#pragma unroll
            for (int i = 0; i < 8; i++)
#pragma unroll
                for (int j = 0; j < 8; j++) acc[i][j] += av[i] * bv[j];
        }
        __syncthreads();
    }

#pragma unroll
    for (int hi = 0; hi < 2; hi++) {
#pragma unroll
        for (int ii = 0; ii < 4; ii++) {
            int m = m0 + ty * 4 + ii + hi * 64;
            if (m >= N_NODES) continue;
            int ai = hi * 4 + ii;
#pragma unroll
            for (int hj = 0; hj < 2; hj++) {
                int n = tx * 4 + hj * 64;
                __half2 p0 = __floats2half2_rn(acc[ai][hj * 4 + 0],
                                               acc[ai][hj * 4 + 1]);
                __half2 p1 = __floats2half2_rn(acc[ai][hj * 4 + 2],
                                               acc[ai][hj * 4 + 3]);
                uint2 u;
                u.x = *(unsigned*)&p0;
                u.y = *(unsigned*)&p1;
                *(uint2*)(Y + (size_t)m * C + n) = u;
            }
        }
    }
}

// ---------------------------------------------------------------------------
extern "C" void kernel_launch(void* const* d_in, const int* in_sizes, int n_in,
                              void* d_out, int out_size) {
    const float* x  = (const float*)d_in[0];
    const int*   ei = (const int*)d_in[1];
    const float* ea = (const float*)d_in[2];
    const float* lw = (const float*)d_in[3];
    const float* lb = (const float*)d_in[4];
    const float* ew = (const float*)d_in[5];
    const float* eb = (const float*)d_in[6];
    float* out = (float*)d_out;

    __half* yA;
    float *xb0, *xb1;
    cudaGetSymbolAddress((void**)&yA, g_y);
    cudaGetSymbolAddress((void**)&xb0, g_xbuf0);
    cudaGetSymbolAddress((void**)&xb1, g_xbuf1);

    const int NODE_BLOCKS = (N_NODES + 255) / 256;
    const int EDGE_BLOCKS = (N_EDGES + 255) / 256;
    const int CNT_BLOCKS  = (N_EDGES / 4 + 255) / 256;
    const int AGG_BLOCKS  = (N_NODES + 7) / 8;        // warp/node, 8 warps/blk
    const int GM_BLOCKS   = (N_NODES + GBM - 1) / GBM;

    // One-time lazy creation of the side stream + fork/join events (created
    // outside capture on the correctness call; reused on the capture call).
    struct Res {
        cudaStream_t s2;
        cudaEvent_t evFork, evJoin;
        Res() {
            cudaStreamCreateWithFlags(&s2, cudaStreamNonBlocking);
            cudaEventCreateWithFlags(&evFork, cudaEventDisableTiming);
            cudaEventCreateWithFlags(&evJoin, cudaEventDisableTiming);
        }
    };
    static Res r;

    // Fork: gemm0 (y0 = x@W0) runs concurrently with the CSR build.
    cudaEventRecord(r.evFork, 0);
    cudaStreamWaitEvent(r.s2, r.evFork, 0);
    gemm_kernel<<<GM_BLOCKS, 256, 0, r.s2>>>(x, lw, yA);
    cudaEventRecord(r.evJoin, r.s2);

    // CSR build (by dst) + per-edge softplus weights, on the capture stream.
    zero_deg_kernel<<<NODE_BLOCKS, 256>>>();
    count_kernel<<<CNT_BLOCKS, 256>>>(ei);
    scan_a_kernel<<<SCAN_NB, SCAN_BLK>>>();
    scan_b_kernel<<<1, 128>>>();
    scan_c_kernel<<<NODE_BLOCKS, 256>>>();
    fill_kernel<<<EDGE_BLOCKS, 256>>>(ei, ea, ew, eb);

    cudaStreamWaitEvent(0, r.evJoin, 0);

    // layer 0: agg over y0, relu+residual(x) -> xb0
    agg_kernel<0, 1><<<AGG_BLOCKS, 256>>>(yA, x, lb, xb0);

    // layer 1
    gemm_kernel<<<GM_BLOCKS, 256>>>(xb0, lw + C * C, yA);
    agg_kernel<1, 1><<<AGG_BLOCKS, 256>>>(yA, xb0, lb + C, xb1);

    // layer 2 (no relu/residual)
    gemm_kernel<<<GM_BLOCKS, 256>>>(xb1, lw + 2 * C * C, yA);
    agg_kernel<2, 0><<<AGG_BLOCKS, 256>>>(yA, xb1, lb + 2 * C, out);
}